// round 16
// baseline (speedup 1.0000x reference)
#include <cuda_runtime.h>
#include <cuda_bf16.h>
#include <cstdint>

// TiThTe: B=4096 independent 3-state RC thermal ODEs, Euler scan over T=8760
// steps with tame() soft-clip. One system/thread, 1 warp/SM, latency bound.
// R14: software-pipelined rotation. Each stage consumes the PREVIOUS step's
// MUFU results at the top, immediately re-issues the next step's three
// rsqrts, and parks the stores/t-muls/forcing-muls inside the MUFU shadow.
// Removes the ~25 cyc/step of issue-order serialization R13 had (STG+f-mul
// +x-chain stacked after r2 completion). Keeps 8-step X/Y ext prefetch and
// templated stride.

#define TAME_C  100000.0f
#define TAME_SQ 1.0e10f

__device__ __forceinline__ float rsq_approx(float x) {
    float y;
    asm("rsqrt.approx.f32 %0, %1;" : "=f"(y) : "f"(x));
    return y;
}
__device__ __forceinline__ float decode_dt(const int* dtp) {
    int dv = dtp[0];
    return (dv > 0 && dv < (1 << 23)) ? (float)dv : __int_as_float(dv);
}

// BLIT > 0: compile-time B (stride folds into STG immediate offsets).
template<int BLIT>
__global__ void __launch_bounds__(32, 1)
tithte_rot(const float* __restrict__ state0,
           const float* __restrict__ params,
           const float* __restrict__ ext,    // (T,3): T_out, heatPower, solarGains
           const int*   __restrict__ dtp,
           float* __restrict__ out,          // (T,B,3)
           int B, int T)
{
    int b = blockIdx.x * 32 + threadIdx.x;
    if (b >= B) return;

    const size_t stride = (size_t)((BLIT > 0) ? BLIT : B) * 3;

    float dtf = decode_dt(dtp);

    float Tin = state0[b * 3 + 0];
    float Th  = state0[b * 3 + 1];
    float Te  = state0[b * 3 + 2];

    float C1 = params[b * 6 + 0], R1 = params[b * 6 + 1];
    float C2 = params[b * 6 + 2], R2 = params[b * 6 + 3];
    float C3 = params[b * 6 + 4], R3 = params[b * 6 + 5];

    float k1  = dtf / C1;
    float nkA = -k1 / R1;
    float nkB = -k1 / R2;
    float cA0 = nkA + nkB;
    float cH0 = -nkB;
    float cE0 = -nkA;
    float k2  = dtf / C2;
    float kC  =  k2 / R2;
    float nkC = -kC;
    float k3  = dtf / C3;
    float kD  =  k3 / R1;
    float kE  =  k3 / R3;
    float cE2 = -(kD + kE);

    float* op = out + (size_t)b * 3;

    // Pipeline registers: r*/t* belong to the step about to be applied;
    // f* is the (already scaled) forcing of the step after that.
    float r0, r1, r2, t0, t1, t2, f0, f1, f2;

    // Stage: apply pending update (step k), store row, compute step k+1's
    // x/q/r/t using f (= forcing k+1), then load f <- forcing k+2 (args).
#define STAGE(To_, hp_, sg_, S_)                                   \
    {                                                              \
        Tin = fmaf(t0, r0, Tin);                                   \
        float A = fmaf(Tin, cA0, f0);                              \
        Th  = fmaf(t1, r1, Th);                                    \
        A = fmaf(Th, cH0, A);                                      \
        Te  = fmaf(t2, r2, Te);                                    \
        float x0 = fmaf(Te, cE0, A);                               \
        r0 = rsq_approx(fmaf(x0, x0, TAME_SQ));                    \
        float x1 = fmaf(Th, nkC, fmaf(Tin, kC, f1));               \
        r1 = rsq_approx(fmaf(x1, x1, TAME_SQ));                    \
        float x2 = fmaf(Te, cE2, fmaf(Tin, kD, f2));               \
        r2 = rsq_approx(fmaf(x2, x2, TAME_SQ));                    \
        t0 = x0 * TAME_C;                                          \
        t1 = x1 * TAME_C;                                          \
        t2 = x2 * TAME_C;                                          \
        __stcs(op + (size_t)(S_) * stride + 0, Tin);               \
        __stcs(op + (size_t)(S_) * stride + 1, Th);                \
        __stcs(op + (size_t)(S_) * stride + 2, Te);                \
        f0 = (sg_) * k1;                                           \
        f1 = (hp_) * k2;                                           \
        f2 = (To_) * kE;                                           \
    }

    // Row triples of an 8-step block held in 6 float4s a0..a5:
    //  r0:(a0.x,a0.y,a0.z) r1:(a0.w,a1.x,a1.y) r2:(a1.z,a1.w,a2.x)
    //  r3:(a2.y,a2.z,a2.w) r4:(a3.x,a3.y,a3.z) r5:(a3.w,a4.x,a4.y)
    //  r6:(a4.z,a4.w,a5.x) r7:(a5.y,a5.z,a5.w)
#define PROC8(a0, a1, a2, a3, a4, a5)                              \
    STAGE(a0.x, a0.y, a0.z, 0)  STAGE(a0.w, a1.x, a1.y, 1)         \
    STAGE(a1.z, a1.w, a2.x, 2)  STAGE(a2.y, a2.z, a2.w, 3)         \
    STAGE(a3.x, a3.y, a3.z, 4)  STAGE(a3.w, a4.x, a4.y, 5)         \
    STAGE(a4.z, a4.w, a5.x, 6)  STAGE(a5.y, a5.z, a5.w, 7)         \
    op += 8 * stride;

    // First block: rows 0,1 feed the prologue; stages consume rows 2..7.
#define PROC6(a0, a1, a2, a3, a4, a5)                              \
    STAGE(a1.z, a1.w, a2.x, 0)  STAGE(a2.y, a2.z, a2.w, 1)         \
    STAGE(a3.x, a3.y, a3.z, 2)  STAGE(a3.w, a4.x, a4.y, 3)         \
    STAGE(a4.z, a4.w, a5.x, 4)  STAGE(a5.y, a5.z, a5.w, 5)         \
    op += 6 * stride;

#define LOAD6(D0, D1, D2, D3, D4, D5, blk)                         \
    {                                                              \
        const float4* _p = e4 + (size_t)(blk) * 6;                 \
        D0 = __ldg(_p + 0); D1 = __ldg(_p + 1); D2 = __ldg(_p + 2);\
        D3 = __ldg(_p + 3); D4 = __ldg(_p + 4); D5 = __ldg(_p + 5);\
    }

    const float4* e4 = (const float4*)ext;
    int nb8 = T >> 3;                     // T % 8 == 0 on this path

    float4 X0, X1, X2, X3, X4, X5, Y0, Y1, Y2, Y3, Y4, Y5;
    LOAD6(X0, X1, X2, X3, X4, X5, 0)
    LOAD6(Y0, Y1, Y2, Y3, Y4, Y5, 1)

    // Prologue: step 0's x/q/r/t from state0 + forcing row 0; f <- row 1.
    {
        float p0 = X0.z * k1;             // sg0
        float p1 = X0.y * k2;             // hp0
        float p2 = X0.x * kE;             // To0
        float x0 = fmaf(Te, cE0, fmaf(Th, cH0, fmaf(Tin, cA0, p0)));
        float x1 = fmaf(Th, nkC, fmaf(Tin, kC, p1));
        float x2 = fmaf(Te, cE2, fmaf(Tin, kD, p2));
        r0 = rsq_approx(fmaf(x0, x0, TAME_SQ));
        r1 = rsq_approx(fmaf(x1, x1, TAME_SQ));
        r2 = rsq_approx(fmaf(x2, x2, TAME_SQ));
        t0 = x0 * TAME_C; t1 = x1 * TAME_C; t2 = x2 * TAME_C;
        f0 = X1.y * k1;                   // sg1
        f1 = X1.x * k2;                   // hp1
        f2 = X0.w * kE;                   // To1
    }

    PROC6(X0, X1, X2, X3, X4, X5)
    LOAD6(X0, X1, X2, X3, X4, X5, (2 < nb8 ? 2 : nb8 - 1))

    int rem = nb8 - 1;                    // blocks 1..nb8-1 still to process
    int npair = rem >> 1;
    for (int p = 0; p < npair; ++p) {
        int ry = 2 * p + 3; if (ry > nb8 - 1) ry = nb8 - 1;
        int rx = 2 * p + 4; if (rx > nb8 - 1) rx = nb8 - 1;
        PROC8(Y0, Y1, Y2, Y3, Y4, Y5)
        LOAD6(Y0, Y1, Y2, Y3, Y4, Y5, ry)
        PROC8(X0, X1, X2, X3, X4, X5)
        LOAD6(X0, X1, X2, X3, X4, X5, rx)
    }
    if (rem & 1) {
        PROC8(Y0, Y1, Y2, Y3, Y4, Y5)
    }

    // Epilogue: stages T-2 and T-1 (forcing args past the end are unused;
    // feed the last row's values).
    {
        float Tl = __ldg(ext + (size_t)(T - 1) * 3 + 0);
        float hl = __ldg(ext + (size_t)(T - 1) * 3 + 1);
        float sl = __ldg(ext + (size_t)(T - 1) * 3 + 2);
        STAGE(Tl, hl, sl, 0)
        op += stride;
        STAGE(Tl, hl, sl, 0)
    }
#undef LOAD6
#undef PROC6
#undef PROC8
#undef STAGE
}

// ---------------- generic fallback (any B, T) ----------------

__global__ void __launch_bounds__(32, 1)
tithte_fallback(const float* __restrict__ state0,
                const float* __restrict__ params,
                const float* __restrict__ ext,
                const int*   __restrict__ dtp,
                float* __restrict__ out,
                int B, int T)
{
    int b = blockIdx.x * blockDim.x + threadIdx.x;
    if (b >= B) return;
    float dtf = decode_dt(dtp);

    float Tin = state0[b * 3 + 0], Th = state0[b * 3 + 1], Te = state0[b * 3 + 2];
    float C1 = params[b * 6 + 0], R1 = params[b * 6 + 1];
    float C2 = params[b * 6 + 2], R2 = params[b * 6 + 3];
    float C3 = params[b * 6 + 4], R3 = params[b * 6 + 5];
    float k1 = dtf / C1, nkA = -k1 / R1, nkB = -k1 / R2;
    float cA0 = nkA + nkB, cH0 = -nkB, cE0 = -nkA;
    float k2 = dtf / C2, kC = k2 / R2, nkC = -kC;
    float k3 = dtf / C3, kD = k3 / R1, kE = k3 / R3, cE2 = -(kD + kE);

    float* op = out + (size_t)b * 3;
    const size_t stride = (size_t)B * 3;
    for (int t = 0; t < T; ++t) {
        float To = __ldg(ext + (size_t)t * 3 + 0);
        float hp = __ldg(ext + (size_t)t * 3 + 1);
        float sg = __ldg(ext + (size_t)t * 3 + 2);
        float f0 = sg * k1, f1 = hp * k2, f2 = To * kE;
        float x0 = fmaf(Te, cE0, fmaf(Th, cH0, fmaf(Tin, cA0, f0)));
        float x1 = fmaf(Th, nkC, fmaf(Tin, kC, f1));
        float x2 = fmaf(Te, cE2, fmaf(Tin, kD, f2));
        float r0 = rsq_approx(fmaf(x0, x0, TAME_SQ));
        float r1 = rsq_approx(fmaf(x1, x1, TAME_SQ));
        float r2 = rsq_approx(fmaf(x2, x2, TAME_SQ));
        Tin = fmaf(x0 * TAME_C, r0, Tin);
        Th  = fmaf(x1 * TAME_C, r1, Th);
        Te  = fmaf(x2 * TAME_C, r2, Te);
        __stcs(op + 0, Tin);
        __stcs(op + 1, Th);
        __stcs(op + 2, Te);
        op += stride;
    }
}

extern "C" void kernel_launch(void* const* d_in, const int* in_sizes, int n_in,
                              void* d_out, int out_size)
{
    const float* state0 = (const float*)d_in[0];   // (B,3)
    const float* params = (const float*)d_in[1];   // (B,6)
    const float* ext    = (const float*)d_in[2];   // (T,3)
    const int*   dtp    = (const int*)d_in[3];     // scalar
    float* out = (float*)d_out;                    // (T,B,3)

    int B = in_sizes[0] / 3;
    int T = in_sizes[2] / 3;
    int grid = (B + 31) / 32;

    if ((T % 8) == 0 && T >= 32) {
        if (B == 4096) {
            tithte_rot<4096><<<grid, 32>>>(state0, params, ext, dtp, out, B, T);
        } else {
            tithte_rot<0><<<grid, 32>>>(state0, params, ext, dtp, out, B, T);
        }
    } else {
        tithte_fallback<<<grid, 32>>>(state0, params, ext, dtp, out, B, T);
    }
}